// round 2
// baseline (speedup 1.0000x reference)
#include <cuda_runtime.h>
#include <math.h>
#include <stdint.h>

#define BS 32
#define NQ 900
#define NC 91
#define NT 30
#define NTT (BS * NT)   // 960 total targets
#define QPB 32          // q-rows per block in cost kernel
#define KLOC 29         // ceil(NQ/32) local columns per lane (lanes 0..3 have 29, rest 28)
#define DINF 1e300

// ---------------------------------------------------------------------------
// Kernel 1: cost matrix C3[b, q, j] for all 960 targets j.
// One block handles QPB q's for one batch b; 8 warps, each warp owns q's.
// ---------------------------------------------------------------------------
__global__ void __launch_bounds__(256) cost_kernel(
    const float* __restrict__ logits,   // (BS, NQ, NC)
    const float* __restrict__ pboxes,   // (BS, NQ, 4) cxcywh
    const int*   __restrict__ tlabels,  // (BS, NT)
    const float* __restrict__ tboxes,   // (BS, NT, 4) cxcywh
    float* __restrict__ out)            // (BS, NQ, NTT)
{
    __shared__ float s_traw[NTT * 4];   // raw cxcywh
    __shared__ float s_txy[NTT * 4];    // xyxy
    __shared__ float s_tarea[NTT];
    __shared__ int   s_tlab[NTT];
    __shared__ float s_prob[8][92];     // per-warp softmax probs

    const int b     = blockIdx.y;
    const int qbase = blockIdx.x * QPB;
    const int tid   = threadIdx.x;

    for (int j = tid; j < NTT; j += blockDim.x) {
        float cx = tboxes[j * 4 + 0];
        float cy = tboxes[j * 4 + 1];
        float w  = tboxes[j * 4 + 2];
        float h  = tboxes[j * 4 + 3];
        s_traw[j * 4 + 0] = cx; s_traw[j * 4 + 1] = cy;
        s_traw[j * 4 + 2] = w;  s_traw[j * 4 + 3] = h;
        float x0 = cx - 0.5f * w, y0 = cy - 0.5f * h;
        float x1 = cx + 0.5f * w, y1 = cy + 0.5f * h;
        s_txy[j * 4 + 0] = x0; s_txy[j * 4 + 1] = y0;
        s_txy[j * 4 + 2] = x1; s_txy[j * 4 + 3] = y1;
        s_tarea[j] = (x1 - x0) * (y1 - y0);
        s_tlab[j] = tlabels[j];
    }
    __syncthreads();

    const int warp = tid >> 5;
    const int lane = tid & 31;

    for (int qi = warp; qi < QPB; qi += 8) {
        const int q = qbase + qi;
        if (q >= NQ) continue;

        // --- softmax over 91 classes (warp-collective) ---
        const float* lg = logits + ((size_t)b * NQ + q) * NC;
        float x0 = (lane      < NC) ? lg[lane]      : -1e30f;
        float x1 = (lane + 32 < NC) ? lg[lane + 32] : -1e30f;
        float x2 = (lane + 64 < NC) ? lg[lane + 64] : -1e30f;
        float m = fmaxf(x0, fmaxf(x1, x2));
        #pragma unroll
        for (int o = 16; o > 0; o >>= 1) m = fmaxf(m, __shfl_xor_sync(0xffffffffu, m, o));
        float e0 = (lane      < NC) ? expf(x0 - m) : 0.f;
        float e1 = (lane + 32 < NC) ? expf(x1 - m) : 0.f;
        float e2 = (lane + 64 < NC) ? expf(x2 - m) : 0.f;
        float s = e0 + e1 + e2;
        #pragma unroll
        for (int o = 16; o > 0; o >>= 1) s += __shfl_xor_sync(0xffffffffu, s, o);
        float inv = 1.0f / s;
        if (lane      < NC) s_prob[warp][lane]      = e0 * inv;
        if (lane + 32 < NC) s_prob[warp][lane + 32] = e1 * inv;
        if (lane + 64 < NC) s_prob[warp][lane + 64] = e2 * inv;
        __syncwarp();

        const float* pb = pboxes + ((size_t)b * NQ + q) * 4;
        float pcx = pb[0], pcy = pb[1], pw = pb[2], ph = pb[3];
        float px0 = pcx - 0.5f * pw, py0 = pcy - 0.5f * ph;
        float px1 = pcx + 0.5f * pw, py1 = pcy + 0.5f * ph;
        float parea = (px1 - px0) * (py1 - py0);

        float* orow = out + ((size_t)b * NQ + q) * NTT;
        for (int j = lane; j < NTT; j += 32) {
            float cc = 1.0f - s_prob[warp][s_tlab[j]];
            float cb = fabsf(pcx - s_traw[j * 4 + 0]) + fabsf(pcy - s_traw[j * 4 + 1])
                     + fabsf(pw  - s_traw[j * 4 + 2]) + fabsf(ph  - s_traw[j * 4 + 3]);
            float tx0 = s_txy[j * 4 + 0], ty0 = s_txy[j * 4 + 1];
            float tx1 = s_txy[j * 4 + 2], ty1 = s_txy[j * 4 + 3];
            float iw = fmaxf(fminf(px1, tx1) - fmaxf(px0, tx0), 0.f);
            float ih = fmaxf(fminf(py1, ty1) - fmaxf(py0, ty0), 0.f);
            float inter = iw * ih;
            float uni = parea + s_tarea[j] - inter;
            float iou = inter / uni;
            float ew = fmaxf(fmaxf(px1, tx1) - fminf(px0, tx0), 0.f);
            float eh = fmaxf(fmaxf(py1, ty1) - fminf(py0, ty0), 0.f);
            float encl = ew * eh;
            float giou = iou - (encl - uni) / encl;
            orow[j] = 5.0f * cb + cc + 2.0f * (1.0f - giou);
        }
    }
}

// ---------------------------------------------------------------------------
// Kernel 2: per-batch optimal assignment, warp-per-problem, scipy-style
// shortest augmenting path (Jonker-Volgenant). 256 threads stage the cost
// slice into shared coalesced; warp 0 solves with zero block barriers.
// Column j owned by lane (j % 32), local index k = j / 32.
// ---------------------------------------------------------------------------
extern __shared__ unsigned char lsa_sh[];

__global__ void __launch_bounds__(256) lsa_kernel(
    const float* __restrict__ C3,
    float* __restrict__ out_pred,
    float* __restrict__ out_tgt)
{
    const int bi  = blockIdx.x;
    const int tid = threadIdx.x;

    // carve shared
    float*  cst     = (float*)lsa_sh;               // NT*NQ  [t][j]
    double* v       = (double*)(cst + NT * NQ);     // NQ
    double* spc     = v + NQ;                       // NQ shortest path costs
    double* u       = spc + NQ;                     // NT
    int* path       = (int*)(u + NT);               // NQ
    int* row4col    = path + NQ;                    // NQ
    int* col4row    = row4col + NQ;                 // NT
    int* SR         = col4row + NT;                 // NT+2
    int* SC         = SR + (NT + 2);                // NT+2

    // stage cost slice transposed to [t][j]; source C3[bi, q, bi*NT + t]
    const float* base = C3 + (size_t)bi * NQ * NTT + (size_t)bi * NT;
    for (int idx = tid; idx < NT * NQ; idx += 256) {
        int j = idx / NT;
        int t = idx - j * NT;
        cst[t * NQ + j] = base[(size_t)j * NTT + t];
    }
    for (int j = tid; j < NQ; j += 256) { v[j] = 0.0; row4col[j] = -1; }
    if (tid < NT) { u[tid] = 0.0; col4row[tid] = -1; }
    __syncthreads();

    if (tid >= 32) return;   // only warp 0 solves
    const int l = tid;
    const unsigned fullmask = (l < 4) ? ((1u << 29) - 1u) : ((1u << 28) - 1u);

    for (int cur_row = 0; cur_row < NT; cur_row++) {
        unsigned rem = fullmask;
        // init shortest path costs to INF for owned columns
        #pragma unroll
        for (int k = 0; k < KLOC; k++) {
            int j = k * 32 + l;
            if (j < NQ) spc[j] = DINF;
        }
        int nSR = 0, nSC = 0;
        double minVal = 0.0;
        int i = cur_row;
        int sink;

        while (true) {
            if (l == 0) SR[nSR] = i;
            nSR++;
            const double u_i = u[i];
            const float* crow = cst + i * NQ;

            double lmin = DINF;
            int lidx = NQ + 1;
            #pragma unroll
            for (int k = 0; k < KLOC; k++) {
                int j = k * 32 + l;
                bool ok = (j < NQ) && ((rem >> k) & 1u);
                if (ok) {
                    double r = minVal + ((double)crow[j] - u_i - v[j]);
                    double s = spc[j];
                    if (r < s) { spc[j] = r; path[j] = i; s = r; }
                    if (s < lmin) { lmin = s; lidx = j; }
                }
            }
            // warp argmin, lowest-index tiebreak (uniform result via xor butterfly)
            #pragma unroll
            for (int off = 16; off > 0; off >>= 1) {
                double ov = __shfl_xor_sync(0xffffffffu, lmin, off);
                int    oi = __shfl_xor_sync(0xffffffffu, lidx, off);
                if (ov < lmin || (ov == lmin && oi < lidx)) { lmin = ov; lidx = oi; }
            }
            minVal = lmin;
            const int j1 = lidx;
            const int r4 = row4col[j1];
            if (r4 < 0) { sink = j1; break; }
            i = r4;
            if (l == (j1 & 31)) rem &= ~(1u << (j1 >> 5));
            if (l == 0) SC[nSC] = j1;
            nSC++;
        }

        __syncwarp();
        if (l == 0) {
            // dual updates
            u[cur_row] += minVal;
            for (int a = 1; a < nSR; a++) {
                int ir = SR[a];
                u[ir] += minVal - spc[col4row[ir]];
            }
            for (int a = 0; a < nSC; a++) {
                int j = SC[a];
                v[j] -= minVal - spc[j];
            }
            // augment along predecessor chain
            int j = sink;
            while (true) {
                int ir = path[j];
                row4col[j] = ir;
                int tmp = col4row[ir];
                col4row[ir] = j;
                j = tmp;
                if (ir == cur_row) break;
            }
        }
        __syncwarp();
    }

    if (l == 0) {
        // rows[t] = assigned query for target t; stable argsort by query
        int ord[NT];
        for (int k = 0; k < NT; k++) ord[k] = k;
        for (int a = 1; a < NT; a++) {
            int key = ord[a]; int kv = col4row[key]; int b2 = a - 1;
            while (b2 >= 0 && col4row[ord[b2]] > kv) { ord[b2 + 1] = ord[b2]; b2--; }
            ord[b2 + 1] = key;
        }
        for (int k = 0; k < NT; k++) {
            out_pred[bi * NT + k] = (float)col4row[ord[k]];
            out_tgt[bi * NT + k]  = (float)ord[k];
        }
    }
}

// ---------------------------------------------------------------------------
extern "C" void kernel_launch(void* const* d_in, const int* in_sizes, int n_in,
                              void* d_out, int out_size)
{
    const float* logits  = (const float*)d_in[0];
    const float* pboxes  = (const float*)d_in[1];
    const int*   tlabels = (const int*)d_in[2];
    const float* tboxes  = (const float*)d_in[3];
    float* out = (float*)d_out;

    dim3 grid((NQ + QPB - 1) / QPB, BS);
    cost_kernel<<<grid, 256>>>(logits, pboxes, tlabels, tboxes, out);

    const size_t lsa_smem =
        (size_t)NT * NQ * sizeof(float)                 // cst
        + (2 * NQ + NT) * sizeof(double)                // v, spc, u
        + (2 * NQ + NT + 2 * (NT + 2)) * sizeof(int);   // path, row4col, col4row, SR, SC
    cudaFuncSetAttribute(lsa_kernel, cudaFuncAttributeMaxDynamicSharedMemorySize,
                         (int)lsa_smem);

    float* out_pred = out + (size_t)BS * NQ * NTT;
    float* out_tgt  = out_pred + (size_t)BS * NT;
    lsa_kernel<<<BS, 256, lsa_smem>>>(out, out_pred, out_tgt);
}

// round 3
// speedup vs baseline: 2.0049x; 2.0049x over previous
#include <cuda_runtime.h>
#include <math.h>
#include <stdint.h>

#define BS 32
#define NQ 900
#define NC 91
#define NT 30
#define NTT (BS * NT)   // 960 total targets
#define QPB 32          // q-rows per block in cost kernel
#define KLOC 29         // ceil(NQ/32) owned columns per lane
#define FINF 3.0e38f

// ---------------------------------------------------------------------------
// Kernel 1: cost matrix C3[b, q, j]. One block = QPB q's of one batch.
// ---------------------------------------------------------------------------
__global__ void __launch_bounds__(256) cost_kernel(
    const float* __restrict__ logits,   // (BS, NQ, NC)
    const float* __restrict__ pboxes,   // (BS, NQ, 4)
    const int*   __restrict__ tlabels,  // (BS, NT)
    const float* __restrict__ tboxes,   // (BS, NT, 4)
    float* __restrict__ out)            // (BS, NQ, NTT)
{
    __shared__ float4 s_traw[NTT];      // cxcywh
    __shared__ float4 s_txy[NTT];       // xyxy
    __shared__ float  s_tarea[NTT];
    __shared__ int    s_tlab[NTT];
    __shared__ float  s_prob[8][92];

    const int b     = blockIdx.y;
    const int qbase = blockIdx.x * QPB;
    const int tid   = threadIdx.x;

    const float4* tb4 = (const float4*)tboxes;
    for (int j = tid; j < NTT; j += 256) {
        float4 bb = tb4[j];
        s_traw[j] = bb;
        float x0 = bb.x - 0.5f * bb.z, y0 = bb.y - 0.5f * bb.w;
        float x1 = bb.x + 0.5f * bb.z, y1 = bb.y + 0.5f * bb.w;
        s_txy[j] = make_float4(x0, y0, x1, y1);
        s_tarea[j] = (x1 - x0) * (y1 - y0);
        s_tlab[j] = tlabels[j];
    }
    __syncthreads();

    const int warp = tid >> 5;
    const int lane = tid & 31;

    for (int qi = warp; qi < QPB; qi += 8) {
        const int q = qbase + qi;
        if (q >= NQ) continue;

        // softmax over 91 classes, warp-collective
        const float* lg = logits + ((size_t)b * NQ + q) * NC;
        float x0 = (lane      < NC) ? lg[lane]      : -FINF;
        float x1 = (lane + 32 < NC) ? lg[lane + 32] : -FINF;
        float x2 = (lane + 64 < NC) ? lg[lane + 64] : -FINF;
        float m = fmaxf(x0, fmaxf(x1, x2));
        #pragma unroll
        for (int o = 16; o > 0; o >>= 1) m = fmaxf(m, __shfl_xor_sync(0xffffffffu, m, o));
        float e0 = (lane      < NC) ? __expf(x0 - m) : 0.f;
        float e1 = (lane + 32 < NC) ? __expf(x1 - m) : 0.f;
        float e2 = (lane + 64 < NC) ? __expf(x2 - m) : 0.f;
        float s = e0 + e1 + e2;
        #pragma unroll
        for (int o = 16; o > 0; o >>= 1) s += __shfl_xor_sync(0xffffffffu, s, o);
        float inv = __frcp_rn(s);
        if (lane      < NC) s_prob[warp][lane]      = e0 * inv;
        if (lane + 32 < NC) s_prob[warp][lane + 32] = e1 * inv;
        if (lane + 64 < NC) s_prob[warp][lane + 64] = e2 * inv;
        __syncwarp();

        const float* pb = pboxes + ((size_t)b * NQ + q) * 4;
        float pcx = pb[0], pcy = pb[1], pw = pb[2], ph = pb[3];
        float px0 = pcx - 0.5f * pw, py0 = pcy - 0.5f * ph;
        float px1 = pcx + 0.5f * pw, py1 = pcy + 0.5f * ph;
        float parea = (px1 - px0) * (py1 - py0);

        float* orow = out + ((size_t)b * NQ + q) * NTT;
        #pragma unroll 3
        for (int j = lane; j < NTT; j += 32) {
            float cc = 1.0f - s_prob[warp][s_tlab[j]];
            float4 tr = s_traw[j];
            float cb = fabsf(pcx - tr.x) + fabsf(pcy - tr.y)
                     + fabsf(pw  - tr.z) + fabsf(ph  - tr.w);
            float4 tx = s_txy[j];
            float iw = fmaxf(fminf(px1, tx.z) - fmaxf(px0, tx.x), 0.f);
            float ih = fmaxf(fminf(py1, tx.w) - fmaxf(py0, tx.y), 0.f);
            float inter = iw * ih;
            float uni = parea + s_tarea[j] - inter;
            float iou = __fdividef(inter, uni);
            float ew = fmaxf(px1, tx.z) - fminf(px0, tx.x);
            float eh = fmaxf(py1, tx.w) - fminf(py0, tx.y);
            float encl = ew * eh;
            float giou = iou - __fdividef(encl - uni, encl);
            orow[j] = fmaf(5.0f, cb, cc) + 2.0f * (1.0f - giou);
        }
    }
}

// ---------------------------------------------------------------------------
// Kernel 2: warp-per-problem shortest-augmenting-path LSA (scipy-style),
// fp32, v/spc in registers (static indexing only), path/bookkeeping in
// separate static shared arrays (no aliasing with dynamic cst).
// Column j owned by lane (j & 31), local slot k = j >> 5.
// ---------------------------------------------------------------------------
__global__ void __launch_bounds__(256) lsa_kernel(
    const float* __restrict__ C3,
    float* __restrict__ out_pred,
    float* __restrict__ out_tgt)
{
    extern __shared__ float cst[];          // [NT][NQ]
    __shared__ float u_s[NT];
    __shared__ int   r4c[NQ];               // row4col
    __shared__ int   c4r[NT];               // col4row
    __shared__ int   path_s[NQ];
    __shared__ int   sc_s[NT + 1];
    __shared__ float scv_s[NT + 1];

    const int bi  = blockIdx.x;
    const int tid = threadIdx.x;

    // stage cost slice transposed to [t][j]; source C3[bi, q, bi*NT + t]
    const float* base = C3 + (size_t)bi * NQ * NTT + (size_t)bi * NT;
    for (int idx = tid; idx < NT * NQ; idx += 256) {
        int j = idx / NT;
        int t = idx - j * NT;
        cst[t * NQ + j] = base[(size_t)j * NTT + t];
    }
    for (int j = tid; j < NQ; j += 256) r4c[j] = -1;
    if (tid < NT) { u_s[tid] = 0.f; c4r[tid] = -1; }
    __syncthreads();

    if (tid >= 32) return;
    const int l = tid;
    const unsigned fullmask = (l < 4) ? 0x1FFFFFFFu : 0x0FFFFFFFu;

    float v_r[KLOC];
    float spc_r[KLOC];
    #pragma unroll
    for (int k = 0; k < KLOC; k++) v_r[k] = 0.f;

    for (int cur = 0; cur < NT; cur++) {
        unsigned rem = fullmask;
        #pragma unroll
        for (int k = 0; k < KLOC; k++) spc_r[k] = FINF;
        float minVal = 0.f;
        int i = cur, sink = -1, nSC = 0;

        while (true) {
            const float um = u_s[i];
            const float* crow = cst + i * NQ;

            // batch-load this row's owned entries (independent LDS)
            float c[KLOC];
            #pragma unroll
            for (int k = 0; k < KLOC; k++) {
                c[k] = (k < 28 || l < 4) ? crow[k * 32 + l] : FINF;
            }

            float lmin = FINF;
            int lidx = 0x7FFFFFFF;
            #pragma unroll
            for (int k = 0; k < KLOC; k++) {
                if ((rem >> k) & 1u) {
                    float r = minVal + (c[k] - um - v_r[k]);
                    if (r < spc_r[k]) { spc_r[k] = r; path_s[k * 32 + l] = i; }
                    if (spc_r[k] < lmin) { lmin = spc_r[k]; lidx = k * 32 + l; }
                }
            }
            // warp argmin, lowest-index tiebreak
            #pragma unroll
            for (int off = 16; off > 0; off >>= 1) {
                float ov = __shfl_xor_sync(0xffffffffu, lmin, off);
                int   oi = __shfl_xor_sync(0xffffffffu, lidx, off);
                if (ov < lmin || (ov == lmin && oi < lidx)) { lmin = ov; lidx = oi; }
            }
            minVal = lmin;
            const int j1 = lidx;
            const int r4 = r4c[j1];
            if (r4 < 0) { sink = j1; break; }
            if (l == (j1 & 31)) rem &= ~(1u << (j1 >> 5));
            if (l == 0) { sc_s[nSC] = j1; scv_s[nSC] = minVal; }
            nSC++;
            i = r4;
        }
        __syncwarp();

        // dual updates: u for visited rows (lane 0), v for removed columns (owners)
        if (l == 0) {
            u_s[cur] += minVal;
            for (int a = 0; a < nSC; a++) {
                int ir = r4c[sc_s[a]];          // row reached via SC[a] (pre-augment)
                u_s[ir] += minVal - scv_s[a];
            }
        }
        for (int a = 0; a < nSC; a++) {
            int j = sc_s[a];
            float d = minVal - scv_s[a];
            int kk = j >> 5, ll = j & 31;
            #pragma unroll
            for (int k = 0; k < KLOC; k++)
                if (k == kk && l == ll) v_r[k] -= d;
        }
        __syncwarp();

        // augment predecessor chain
        if (l == 0) {
            int j = sink;
            while (true) {
                int ir = path_s[j];
                r4c[j] = ir;
                int tmp = c4r[ir];
                c4r[ir] = j;
                j = tmp;
                if (ir == cur) break;
            }
        }
        __syncwarp();
    }

    if (l == 0) {
        int ord[NT];
        for (int k = 0; k < NT; k++) ord[k] = k;
        for (int a = 1; a < NT; a++) {
            int key = ord[a]; int kv = c4r[key]; int b2 = a - 1;
            while (b2 >= 0 && c4r[ord[b2]] > kv) { ord[b2 + 1] = ord[b2]; b2--; }
            ord[b2 + 1] = key;
        }
        for (int k = 0; k < NT; k++) {
            out_pred[bi * NT + k] = (float)c4r[ord[k]];
            out_tgt[bi * NT + k]  = (float)ord[k];
        }
    }
}

// ---------------------------------------------------------------------------
extern "C" void kernel_launch(void* const* d_in, const int* in_sizes, int n_in,
                              void* d_out, int out_size)
{
    const float* logits  = (const float*)d_in[0];
    const float* pboxes  = (const float*)d_in[1];
    const int*   tlabels = (const int*)d_in[2];
    const float* tboxes  = (const float*)d_in[3];
    float* out = (float*)d_out;

    dim3 grid((NQ + QPB - 1) / QPB, BS);
    cost_kernel<<<grid, 256>>>(logits, pboxes, tlabels, tboxes, out);

    const size_t lsa_smem = (size_t)NT * NQ * sizeof(float);
    cudaFuncSetAttribute(lsa_kernel, cudaFuncAttributeMaxDynamicSharedMemorySize,
                         (int)lsa_smem);

    float* out_pred = out + (size_t)BS * NQ * NTT;
    float* out_tgt  = out_pred + (size_t)BS * NT;
    lsa_kernel<<<BS, 256, lsa_smem>>>(out, out_pred, out_tgt);
}

// round 4
// speedup vs baseline: 4.4059x; 2.1976x over previous
#include <cuda_runtime.h>
#include <math.h>
#include <stdint.h>

#define BS 32
#define NQ 900
#define NC 91
#define NT 30
#define NTT (BS * NT)   // 960
#define QPB 32          // q's per cost block
#define NCH (NTT / 32)  // 30 target chunks
#define KLOC 29         // owned columns per lane in LSA
#define FINF 3.0e38f

// ---------------------------------------------------------------------------
// Kernel 1: cost matrix. Phase 1: per-q softmax+box into shared.
// Phase 2: lane owns one target (registers), loops over q's. Coalesced STG.
// ---------------------------------------------------------------------------
__global__ void __launch_bounds__(256) cost_kernel(
    const float* __restrict__ logits,   // (BS, NQ, NC)
    const float* __restrict__ pboxes,   // (BS, NQ, 4)
    const int*   __restrict__ tlabels,  // (BS, NT)
    const float* __restrict__ tboxes,   // (BS, NT, 4)
    float* __restrict__ out)            // (BS, NQ, NTT)
{
    __shared__ float  s_prob[QPB][92];
    __shared__ float4 s_pba[QPB];    // cx,cy,w,h
    __shared__ float4 s_pbb[QPB];    // x0,y0,x1,y1
    __shared__ float  s_parea[QPB];

    const int b     = blockIdx.y;
    const int qbase = blockIdx.x * QPB;
    const int tid   = threadIdx.x;
    const int warp  = tid >> 5;
    const int lane  = tid & 31;
    const int qlim  = min(QPB, NQ - qbase);

    // ---- phase 1: softmax per q (one warp per q, strided) ----
    for (int qi = warp; qi < qlim; qi += 8) {
        const float* lg = logits + ((size_t)b * NQ + qbase + qi) * NC;
        float x0 = (lane      < NC) ? lg[lane]      : -FINF;
        float x1 = (lane + 32 < NC) ? lg[lane + 32] : -FINF;
        float x2 = (lane + 64 < NC) ? lg[lane + 64] : -FINF;
        float m = fmaxf(x0, fmaxf(x1, x2));
        #pragma unroll
        for (int o = 16; o > 0; o >>= 1) m = fmaxf(m, __shfl_xor_sync(0xffffffffu, m, o));
        float e0 = (lane      < NC) ? __expf(x0 - m) : 0.f;
        float e1 = (lane + 32 < NC) ? __expf(x1 - m) : 0.f;
        float e2 = (lane + 64 < NC) ? __expf(x2 - m) : 0.f;
        float s = e0 + e1 + e2;
        #pragma unroll
        for (int o = 16; o > 0; o >>= 1) s += __shfl_xor_sync(0xffffffffu, s, o);
        float inv = __frcp_rn(s);
        if (lane      < NC) s_prob[qi][lane]      = e0 * inv;
        if (lane + 32 < NC) s_prob[qi][lane + 32] = e1 * inv;
        if (lane + 64 < NC) s_prob[qi][lane + 64] = e2 * inv;
    }
    if (tid < qlim) {
        const float* pb = pboxes + ((size_t)b * NQ + qbase + tid) * 4;
        float cx = pb[0], cy = pb[1], w = pb[2], h = pb[3];
        s_pba[tid] = make_float4(cx, cy, w, h);
        float x0 = cx - 0.5f * w, y0 = cy - 0.5f * h;
        float x1 = cx + 0.5f * w, y1 = cy + 0.5f * h;
        s_pbb[tid] = make_float4(x0, y0, x1, y1);
        s_parea[tid] = (x1 - x0) * (y1 - y0);
    }
    __syncthreads();

    // ---- phase 2: lane = one target, loop over q's ----
    const float4* tb4 = (const float4*)tboxes;
    for (int c = warp; c < NCH; c += 8) {
        const int j = c * 32 + lane;
        float4 tr = tb4[j];
        float tx0 = tr.x - 0.5f * tr.z, ty0 = tr.y - 0.5f * tr.w;
        float tx1 = tr.x + 0.5f * tr.z, ty1 = tr.y + 0.5f * tr.w;
        float tarea = (tx1 - tx0) * (ty1 - ty0);
        const int lab = tlabels[j];
        float* ocol = out + (size_t)b * NQ * NTT + (size_t)qbase * NTT + j;

        #pragma unroll 4
        for (int qi = 0; qi < qlim; qi++) {
            float4 pa  = s_pba[qi];
            float4 pbx = s_pbb[qi];
            float parea = s_parea[qi];
            float prob  = s_prob[qi][lab];
            float cb = fabsf(pa.x - tr.x) + fabsf(pa.y - tr.y)
                     + fabsf(pa.z - tr.z) + fabsf(pa.w - tr.w);
            float iw = fmaxf(fminf(pbx.z, tx1) - fmaxf(pbx.x, tx0), 0.f);
            float ih = fmaxf(fminf(pbx.w, ty1) - fmaxf(pbx.y, ty0), 0.f);
            float inter = iw * ih;
            float uni = parea + tarea - inter;
            float ew = fmaxf(pbx.z, tx1) - fminf(pbx.x, tx0);
            float eh = fmaxf(pbx.w, ty1) - fminf(pbx.y, ty0);
            // C = 5*cb + 5 - prob - 2*inter/uni - 2*uni/encl
            float res = fmaf(5.0f, cb, 5.0f) - prob
                      - 2.0f * __fdividef(inter, uni)
                      - 2.0f * __fdividef(uni, ew * eh);
            ocol[(size_t)qi * NTT] = res;
        }
    }
}

// ---------------------------------------------------------------------------
// Kernel 2: warp-per-problem exact JV with row-reduction + greedy init.
// 8 warps stage cost + compute row mins; warp 0 solves (no block barriers
// after init). Column j owned by lane (j & 31), slot k = j >> 5.
// ---------------------------------------------------------------------------
__global__ void __launch_bounds__(256) lsa_kernel(
    const float* __restrict__ C3,
    float* __restrict__ out_pred,
    float* __restrict__ out_tgt)
{
    extern __shared__ float cst[];      // [NT][NQ]
    __shared__ float u_s[NT];
    __shared__ int   rarg_s[NT];
    __shared__ int   r4c[NQ];
    __shared__ int   c4r[NT];
    __shared__ int   path_s[NQ];
    __shared__ int   sc_s[NT + 1];
    __shared__ float scv_s[NT + 1];
    __shared__ int   free_s[NT];
    __shared__ int   nfree_s;

    const int bi  = blockIdx.x;
    const int tid = threadIdx.x;

    // stage cost slice transposed to [t][j]; source C3[bi, q, bi*NT + t]
    const float* base = C3 + (size_t)bi * NQ * NTT + (size_t)bi * NT;
    for (int idx = tid; idx < NT * NQ; idx += 256) {
        int j = idx / NT;
        int t = idx - j * NT;
        cst[t * NQ + j] = base[(size_t)j * NTT + t];
    }
    for (int j = tid; j < NQ; j += 256) r4c[j] = -1;
    if (tid < NT) c4r[tid] = -1;
    __syncthreads();

    // row mins + argmins (8 warps)
    {
        const int w = tid >> 5, ln = tid & 31;
        for (int t = w; t < NT; t += 8) {
            const float* crow = cst + t * NQ;
            float lmin = FINF; int lidx = 0x7FFFFFFF;
            #pragma unroll
            for (int k = 0; k < KLOC; k++) {
                int j = k * 32 + ln;
                if (j < NQ) {
                    float cv = crow[j];
                    if (cv < lmin) { lmin = cv; lidx = j; }
                }
            }
            #pragma unroll
            for (int off = 16; off > 0; off >>= 1) {
                float ov = __shfl_xor_sync(0xffffffffu, lmin, off);
                int   oi = __shfl_xor_sync(0xffffffffu, lidx, off);
                if (ov < lmin || (ov == lmin && oi < lidx)) { lmin = ov; lidx = oi; }
            }
            if (ln == 0) { u_s[t] = lmin; rarg_s[t] = lidx; }
        }
    }
    __syncthreads();
    if (tid >= 32) return;
    const int l = tid;

    // greedy assignment on tight edges (u = rowmin, v = 0)
    if (l == 0) {
        int nf = 0;
        for (int t = 0; t < NT; t++) {
            int j = rarg_s[t];
            if (r4c[j] < 0) { r4c[j] = t; c4r[t] = j; }
            else free_s[nf++] = t;
        }
        nfree_s = nf;
    }
    __syncwarp();
    const int nfree = nfree_s;
    const unsigned fullmask = (l < 4) ? 0x1FFFFFFFu : 0x0FFFFFFFu;

    float v_r[KLOC];
    float spc_r[KLOC];
    #pragma unroll
    for (int k = 0; k < KLOC; k++) v_r[k] = 0.f;

    for (int fi = 0; fi < nfree; fi++) {
        const int cur = free_s[fi];
        unsigned rem = fullmask;
        #pragma unroll
        for (int k = 0; k < KLOC; k++) spc_r[k] = FINF;
        float minVal = 0.f;
        int i = cur, sink = -1, nSC = 0;

        while (true) {
            const float um = u_s[i];
            const float* crow = cst + i * NQ;

            float c[KLOC];
            #pragma unroll
            for (int k = 0; k < KLOC; k++)
                c[k] = (k < 28 || l < 4) ? crow[k * 32 + l] : FINF;

            float lmin = FINF;
            int lidx = 0x7FFFFFFF;
            #pragma unroll
            for (int k = 0; k < KLOC; k++) {
                if ((rem >> k) & 1u) {
                    float r = minVal + (c[k] - um - v_r[k]);
                    if (r < spc_r[k]) { spc_r[k] = r; path_s[k * 32 + l] = i; }
                    if (spc_r[k] < lmin) { lmin = spc_r[k]; lidx = k * 32 + l; }
                }
            }
            #pragma unroll
            for (int off = 16; off > 0; off >>= 1) {
                float ov = __shfl_xor_sync(0xffffffffu, lmin, off);
                int   oi = __shfl_xor_sync(0xffffffffu, lidx, off);
                if (ov < lmin || (ov == lmin && oi < lidx)) { lmin = ov; lidx = oi; }
            }
            minVal = lmin;
            const int j1 = lidx;
            const int r4 = r4c[j1];
            if (r4 < 0) { sink = j1; break; }
            if (l == (j1 & 31)) rem &= ~(1u << (j1 >> 5));
            if (l == 0) { sc_s[nSC] = j1; scv_s[nSC] = minVal; }
            nSC++;
            i = r4;
        }
        __syncwarp();

        if (l == 0) {
            u_s[cur] += minVal;
            for (int a = 0; a < nSC; a++) {
                int ir = r4c[sc_s[a]];          // pre-augment matching
                u_s[ir] += minVal - scv_s[a];
            }
        }
        for (int a = 0; a < nSC; a++) {
            int j = sc_s[a];
            float d = minVal - scv_s[a];
            int kk = j >> 5, ll = j & 31;
            #pragma unroll
            for (int k = 0; k < KLOC; k++)
                if (k == kk && l == ll) v_r[k] -= d;
        }
        __syncwarp();

        if (l == 0) {
            int j = sink;
            while (true) {
                int ir = path_s[j];
                r4c[j] = ir;
                int tmp = c4r[ir];
                c4r[ir] = j;
                j = tmp;
                if (ir == cur) break;
            }
        }
        __syncwarp();
    }

    if (l == 0) {
        int ord[NT];
        for (int k = 0; k < NT; k++) ord[k] = k;
        for (int a = 1; a < NT; a++) {
            int key = ord[a]; int kv = c4r[key]; int b2 = a - 1;
            while (b2 >= 0 && c4r[ord[b2]] > kv) { ord[b2 + 1] = ord[b2]; b2--; }
            ord[b2 + 1] = key;
        }
        for (int k = 0; k < NT; k++) {
            out_pred[bi * NT + k] = (float)c4r[ord[k]];
            out_tgt[bi * NT + k]  = (float)ord[k];
        }
    }
}

// ---------------------------------------------------------------------------
extern "C" void kernel_launch(void* const* d_in, const int* in_sizes, int n_in,
                              void* d_out, int out_size)
{
    const float* logits  = (const float*)d_in[0];
    const float* pboxes  = (const float*)d_in[1];
    const int*   tlabels = (const int*)d_in[2];
    const float* tboxes  = (const float*)d_in[3];
    float* out = (float*)d_out;

    dim3 grid((NQ + QPB - 1) / QPB, BS);
    cost_kernel<<<grid, 256>>>(logits, pboxes, tlabels, tboxes, out);

    const size_t lsa_smem = (size_t)NT * NQ * sizeof(float);
    cudaFuncSetAttribute(lsa_kernel, cudaFuncAttributeMaxDynamicSharedMemorySize,
                         (int)lsa_smem);

    float* out_pred = out + (size_t)BS * NQ * NTT;
    float* out_tgt  = out_pred + (size_t)BS * NT;
    lsa_kernel<<<BS, 256, lsa_smem>>>(out, out_pred, out_tgt);
}

// round 5
// speedup vs baseline: 5.5953x; 1.2699x over previous
#include <cuda_runtime.h>
#include <math.h>
#include <stdint.h>

#define BS 32
#define NQ 900
#define NC 91
#define NT 30
#define NTT (BS * NT)   // 960
#define QPB 32
#define NCH (NTT / 32)  // 30
#define KLOC 29
#define FINF 3.0e38f

__device__ float g_diag[BS * NT * NQ];   // [b][t][q] diagonal cost slices

// order-preserving float->uint key (total order incl. negatives)
__device__ __forceinline__ unsigned fkey(float f) {
    unsigned b = __float_as_uint(f);
    return (b & 0x80000000u) ? ~b : (b | 0x80000000u);
}
__device__ __forceinline__ float funkey(unsigned k) {
    unsigned b = (k & 0x80000000u) ? (k & 0x7FFFFFFFu) : ~k;
    return __uint_as_float(b);
}

// ---------------------------------------------------------------------------
// Kernel 1: cost matrix + transposed diag-slice scratch.
// ---------------------------------------------------------------------------
__global__ void __launch_bounds__(256) cost_kernel(
    const float* __restrict__ logits,
    const float* __restrict__ pboxes,
    const int*   __restrict__ tlabels,
    const float* __restrict__ tboxes,
    float* __restrict__ out)
{
    __shared__ float  s_prob[QPB][92];
    __shared__ float4 s_pba[QPB];
    __shared__ float4 s_pbb[QPB];
    __shared__ float  s_parea[QPB];

    const int b     = blockIdx.y;
    const int qbase = blockIdx.x * QPB;
    const int tid   = threadIdx.x;
    const int warp  = tid >> 5;
    const int lane  = tid & 31;
    const int qlim  = min(QPB, NQ - qbase);

    for (int qi = warp; qi < qlim; qi += 8) {
        const float* lg = logits + ((size_t)b * NQ + qbase + qi) * NC;
        float x0 = (lane      < NC) ? lg[lane]      : -FINF;
        float x1 = (lane + 32 < NC) ? lg[lane + 32] : -FINF;
        float x2 = (lane + 64 < NC) ? lg[lane + 64] : -FINF;
        float m = fmaxf(x0, fmaxf(x1, x2));
        #pragma unroll
        for (int o = 16; o > 0; o >>= 1) m = fmaxf(m, __shfl_xor_sync(0xffffffffu, m, o));
        float e0 = (lane      < NC) ? __expf(x0 - m) : 0.f;
        float e1 = (lane + 32 < NC) ? __expf(x1 - m) : 0.f;
        float e2 = (lane + 64 < NC) ? __expf(x2 - m) : 0.f;
        float s = e0 + e1 + e2;
        #pragma unroll
        for (int o = 16; o > 0; o >>= 1) s += __shfl_xor_sync(0xffffffffu, s, o);
        float inv = __frcp_rn(s);
        if (lane      < NC) s_prob[qi][lane]      = e0 * inv;
        if (lane + 32 < NC) s_prob[qi][lane + 32] = e1 * inv;
        if (lane + 64 < NC) s_prob[qi][lane + 64] = e2 * inv;
    }
    if (tid < qlim) {
        const float* pb = pboxes + ((size_t)b * NQ + qbase + tid) * 4;
        float cx = pb[0], cy = pb[1], w = pb[2], h = pb[3];
        s_pba[tid] = make_float4(cx, cy, w, h);
        float x0 = cx - 0.5f * w, y0 = cy - 0.5f * h;
        float x1 = cx + 0.5f * w, y1 = cy + 0.5f * h;
        s_pbb[tid] = make_float4(x0, y0, x1, y1);
        s_parea[tid] = (x1 - x0) * (y1 - y0);
    }
    __syncthreads();

    const float4* tb4 = (const float4*)tboxes;
    for (int c = warp; c < NCH; c += 8) {
        const int j = c * 32 + lane;
        float4 tr = tb4[j];
        float tx0 = tr.x - 0.5f * tr.z, ty0 = tr.y - 0.5f * tr.w;
        float tx1 = tr.x + 0.5f * tr.z, ty1 = tr.y + 0.5f * tr.w;
        float tarea = (tx1 - tx0) * (ty1 - ty0);
        const int lab = tlabels[j];
        float* ocol = out + (size_t)b * NQ * NTT + (size_t)qbase * NTT + j;

        const int tdiag = j - b * NT;
        float* srow = (tdiag >= 0 && tdiag < NT)
                    ? g_diag + ((size_t)b * NT + tdiag) * NQ + qbase : (float*)0;

        #pragma unroll 4
        for (int qi = 0; qi < qlim; qi++) {
            float4 pa  = s_pba[qi];
            float4 pbx = s_pbb[qi];
            float parea = s_parea[qi];
            float prob  = s_prob[qi][lab];
            float cb = fabsf(pa.x - tr.x) + fabsf(pa.y - tr.y)
                     + fabsf(pa.z - tr.z) + fabsf(pa.w - tr.w);
            float iw = fmaxf(fminf(pbx.z, tx1) - fmaxf(pbx.x, tx0), 0.f);
            float ih = fmaxf(fminf(pbx.w, ty1) - fmaxf(pbx.y, ty0), 0.f);
            float inter = iw * ih;
            float uni = parea + tarea - inter;
            float ew = fmaxf(pbx.z, tx1) - fminf(pbx.x, tx0);
            float eh = fmaxf(pbx.w, ty1) - fminf(pbx.y, ty0);
            float encl = ew * eh;
            // 2*inter/uni + 2*uni/encl == 2*(inter*encl + uni^2)/(uni*encl)
            float num = 2.0f * fmaf(inter, encl, uni * uni);
            float res = fmaf(5.0f, cb, 5.0f) - prob - __fdividef(num, uni * encl);
            ocol[(size_t)qi * NTT] = res;
            if (srow) srow[qi] = res;
        }
    }
}

// ---------------------------------------------------------------------------
// Kernel 2: warp-per-problem exact JV, greedy row-min init, rows read
// directly from L2-hot g_diag (no shared cost tile).
// ---------------------------------------------------------------------------
__global__ void __launch_bounds__(256) lsa_kernel(
    float* __restrict__ out_pred,
    float* __restrict__ out_tgt)
{
    __shared__ float u_s[NT];
    __shared__ int   rarg_s[NT];
    __shared__ int   r4c[NQ];
    __shared__ int   c4r[NT];
    __shared__ int   path_s[NQ];
    __shared__ int   sc_s[NT + 1];
    __shared__ float scv_s[NT + 1];
    __shared__ int   free_s[NT];
    __shared__ int   nfree_s;

    const int bi  = blockIdx.x;
    const int tid = threadIdx.x;
    const float* dslice = g_diag + (size_t)bi * NT * NQ;

    for (int j = tid; j < NQ; j += 256) r4c[j] = -1;
    if (tid < NT) c4r[tid] = -1;

    // row mins (8 warps in parallel)
    {
        const int w = tid >> 5, ln = tid & 31;
        for (int t = w; t < NT; t += 8) {
            const float* crow = dslice + t * NQ;
            unsigned long long best = ~0ull;
            #pragma unroll
            for (int k = 0; k < KLOC; k++) {
                int j = k * 32 + ln;
                if (j < NQ) {
                    unsigned long long p = ((unsigned long long)fkey(crow[j]) << 32) | (unsigned)j;
                    if (p < best) best = p;
                }
            }
            #pragma unroll
            for (int off = 16; off > 0; off >>= 1) {
                unsigned long long o = __shfl_xor_sync(0xffffffffu, best, off);
                if (o < best) best = o;
            }
            if (ln == 0) {
                u_s[t] = funkey((unsigned)(best >> 32));
                rarg_s[t] = (int)(best & 0xFFFFFFFFu);
            }
        }
    }
    __syncthreads();
    if (tid >= 32) return;
    const int l = tid;

    if (l == 0) {
        int nf = 0;
        for (int t = 0; t < NT; t++) {
            int j = rarg_s[t];
            if (r4c[j] < 0) { r4c[j] = t; c4r[t] = j; }
            else free_s[nf++] = t;
        }
        nfree_s = nf;
    }
    __syncwarp();
    const int nfree = nfree_s;
    const unsigned fullmask = (l < 4) ? 0x1FFFFFFFu : 0x0FFFFFFFu;

    float v_r[KLOC];
    float spc_r[KLOC];
    #pragma unroll
    for (int k = 0; k < KLOC; k++) v_r[k] = 0.f;

    for (int fi = 0; fi < nfree; fi++) {
        const int cur = free_s[fi];
        unsigned rem = fullmask;
        #pragma unroll
        for (int k = 0; k < KLOC; k++) spc_r[k] = FINF;
        float minVal = 0.f;
        int i = cur, sink = -1, nSC = 0;

        while (true) {
            const float um = u_s[i];
            const float* crow = dslice + i * NQ;

            float c[KLOC];
            #pragma unroll
            for (int k = 0; k < KLOC; k++)
                c[k] = (k < 28 || l < 4) ? crow[k * 32 + l] : FINF;

            // update spc + 4-way interleaved packed argmin (low depth)
            unsigned long long b0 = ~0ull, b1 = ~0ull, b2 = ~0ull, b3 = ~0ull;
            #pragma unroll
            for (int k = 0; k < KLOC; k++) {
                if ((rem >> k) & 1u) {
                    float r = minVal + (c[k] - um - v_r[k]);
                    if (r < spc_r[k]) { spc_r[k] = r; path_s[k * 32 + l] = i; }
                    unsigned long long p =
                        ((unsigned long long)fkey(spc_r[k]) << 32) | (unsigned)(k * 32 + l);
                    switch (k & 3) {
                        case 0: if (p < b0) b0 = p; break;
                        case 1: if (p < b1) b1 = p; break;
                        case 2: if (p < b2) b2 = p; break;
                        default: if (p < b3) b3 = p; break;
                    }
                }
            }
            unsigned long long best = b0;
            if (b1 < best) best = b1;
            if (b2 < best) best = b2;
            if (b3 < best) best = b3;
            #pragma unroll
            for (int off = 16; off > 0; off >>= 1) {
                unsigned long long o = __shfl_xor_sync(0xffffffffu, best, off);
                if (o < best) best = o;
            }
            minVal = funkey((unsigned)(best >> 32));
            const int j1 = (int)(best & 0xFFFFFFFFu);
            const int r4 = r4c[j1];
            if (r4 < 0) { sink = j1; break; }
            if (l == (j1 & 31)) rem &= ~(1u << (j1 >> 5));
            if (l == 0) { sc_s[nSC] = j1; scv_s[nSC] = minVal; }
            nSC++;
            i = r4;
        }
        __syncwarp();

        if (l == 0) {
            u_s[cur] += minVal;
            for (int a = 0; a < nSC; a++) {
                int ir = r4c[sc_s[a]];
                u_s[ir] += minVal - scv_s[a];
            }
        }
        for (int a = 0; a < nSC; a++) {
            int j = sc_s[a];
            float d = minVal - scv_s[a];
            int kk = j >> 5, ll = j & 31;
            #pragma unroll
            for (int k = 0; k < KLOC; k++)
                if (k == kk && l == ll) v_r[k] -= d;
        }
        __syncwarp();

        if (l == 0) {
            int j = sink;
            while (true) {
                int ir = path_s[j];
                r4c[j] = ir;
                int tmp = c4r[ir];
                c4r[ir] = j;
                j = tmp;
                if (ir == cur) break;
            }
        }
        __syncwarp();
    }

    if (l == 0) {
        int ord[NT];
        for (int k = 0; k < NT; k++) ord[k] = k;
        for (int a = 1; a < NT; a++) {
            int key = ord[a]; int kv = c4r[key]; int b2i = a - 1;
            while (b2i >= 0 && c4r[ord[b2i]] > kv) { ord[b2i + 1] = ord[b2i]; b2i--; }
            ord[b2i + 1] = key;
        }
        for (int k = 0; k < NT; k++) {
            out_pred[bi * NT + k] = (float)c4r[ord[k]];
            out_tgt[bi * NT + k]  = (float)ord[k];
        }
    }
}

// ---------------------------------------------------------------------------
extern "C" void kernel_launch(void* const* d_in, const int* in_sizes, int n_in,
                              void* d_out, int out_size)
{
    const float* logits  = (const float*)d_in[0];
    const float* pboxes  = (const float*)d_in[1];
    const int*   tlabels = (const int*)d_in[2];
    const float* tboxes  = (const float*)d_in[3];
    float* out = (float*)d_out;

    dim3 grid((NQ + QPB - 1) / QPB, BS);
    cost_kernel<<<grid, 256>>>(logits, pboxes, tlabels, tboxes, out);

    float* out_pred = out + (size_t)BS * NQ * NTT;
    float* out_tgt  = out_pred + (size_t)BS * NT;
    lsa_kernel<<<BS, 256>>>(out_pred, out_tgt);
}